// round 7
// baseline (speedup 1.0000x reference)
#include <cuda_runtime.h>
#include <cstdint>

// Fused CosFace margin + scale. 512 threads x 2 float4 per thread, 4 CTAs/SM.
// out[r, c] = (logits[r, c] - (c == labels[r] ? M : 0)) * S
// logits: [4096, 50257] fp32 ; labels: [4096] int32 ; out: fp32.
// n4 = 4096*50257/4 = 51,463,168 = 1024 * 50257 exactly -> grid of 50257 blocks
// of 512 threads x 2 float4 covers everything with NO bounds checks.
// labels[r] == -1 never equals a column index, so no validity check needed.

static constexpr float S = 64.0f;
static constexpr float M = 0.35f;
static constexpr unsigned NC = 50257u;
static constexpr unsigned TPB = 512u;
static constexpr unsigned ILP = 2u;

__device__ __forceinline__ void apply_margin(float4& v, int lbl, unsigned row,
                                             unsigned col,
                                             const int* __restrict__ labels) {
    if (col <= NC - 4u) {
        // All 4 elements in the same row (common case).
        unsigned d = (unsigned)lbl - col;   // wraps huge if no match / lbl == -1
        if (d < 4u) (&v.x)[d] -= M;
    } else {
        // Straddles a row boundary (rare: ~3 float4s per 50257 elements).
        float* p = &v.x;
        unsigned r = row, c = col;
        #pragma unroll
        for (int k = 0; k < 4; k++) {
            if (c == NC) { c = 0u; r += 1u; }
            if ((unsigned)__ldg(&labels[r]) == c) p[k] -= M;
            c += 1u;
        }
    }
}

__global__ void __launch_bounds__(TPB, 4)
cosface_fused512_kernel(const float4* __restrict__ in,
                        float4* __restrict__ out,
                        const int* __restrict__ labels) {
    const unsigned i0 = blockIdx.x * (TPB * ILP) + threadIdx.x;
    const unsigned i1 = i0 + TPB;

    // Front-batch both stream loads.
    float4 v0 = __ldcs(&in[i0]);
    float4 v1 = __ldcs(&in[i1]);

    // One division serves both chunks.
    unsigned e0 = i0 * 4u;
    unsigned row0 = e0 / NC;                // umulhi magic div
    unsigned col0 = e0 - row0 * NC;
    // Second chunk is +2048 elements; wraps at most one row (2048+4 << NC).
    unsigned row1 = row0, col1 = col0 + TPB * 4u;
    if (col1 >= NC) { col1 -= NC; row1 += 1u; }

    // Issue both label loads up front (L1-resident broadcast; raises MLP).
    int lbl0 = __ldg(&labels[row0]);
    int lbl1 = __ldg(&labels[row1]);

    apply_margin(v0, lbl0, row0, col0, labels);
    apply_margin(v1, lbl1, row1, col1, labels);

    v0.x *= S; v0.y *= S; v0.z *= S; v0.w *= S;
    v1.x *= S; v1.y *= S; v1.z *= S; v1.w *= S;

    __stcs(&out[i0], v0);
    __stcs(&out[i1], v1);
}

extern "C" void kernel_launch(void* const* d_in, const int* in_sizes, int n_in,
                              void* d_out, int out_size) {
    const float* logits = (const float*)d_in[0];
    const int* labels = (const int*)d_in[1];
    float* out = (float*)d_out;

    unsigned total = (unsigned)in_sizes[0];       // 4096 * 50257
    unsigned n4 = total / 4u;
    unsigned per_block = TPB * ILP;               // 1024 float4s per block
    unsigned blocks = (n4 + per_block - 1u) / per_block;   // = 50257 exactly
    cosface_fused512_kernel<<<blocks, TPB>>>(
        (const float4*)logits, (float4*)out, labels);
}

// round 8
// speedup vs baseline: 1.0008x; 1.0008x over previous
#include <cuda_runtime.h>
#include <cstdint>

// Fused CosFace margin + scale. 512 threads x 2 float4 per thread.
// out[r, c] = (logits[r, c] - (c == labels[r] ? M : 0)) * S
// logits: [4096, 50257] fp32 ; labels: [4096] int32 ; out: fp32.
// n4 = 4096*50257/4 = 51,463,168 = 1024 * 50257 exactly -> grid of 50257 blocks
// of 512 threads x 2 float4 covers everything with NO bounds checks.
// labels[r] == -1 never equals a column index, so no validity check needed.
//
// Measured roofline: ~228-229us kernel @ ~6.98 TB/s (88% DRAM), compute fully
// hidden. This configuration merges the two best-measured variants:
// hoisted dual label loads (R7 kernel best) + unpinned occupancy (R6 regs=30).

static constexpr float S = 64.0f;
static constexpr float M = 0.35f;
static constexpr unsigned NC = 50257u;
static constexpr unsigned TPB = 512u;
static constexpr unsigned ILP = 2u;

__device__ __forceinline__ void apply_margin(float4& v, int lbl, unsigned row,
                                             unsigned col,
                                             const int* __restrict__ labels) {
    if (col <= NC - 4u) {
        // All 4 elements in the same row (common case).
        unsigned d = (unsigned)lbl - col;   // wraps huge if no match / lbl == -1
        if (d < 4u) (&v.x)[d] -= M;
    } else {
        // Straddles a row boundary (rare: ~3 float4s per 50257 elements).
        float* p = &v.x;
        unsigned r = row, c = col;
        #pragma unroll
        for (int k = 0; k < 4; k++) {
            if (c == NC) { c = 0u; r += 1u; }
            if ((unsigned)__ldg(&labels[r]) == c) p[k] -= M;
            c += 1u;
        }
    }
}

__global__ void __launch_bounds__(TPB)
cosface_fused512_kernel(const float4* __restrict__ in,
                        float4* __restrict__ out,
                        const int* __restrict__ labels) {
    const unsigned i0 = blockIdx.x * (TPB * ILP) + threadIdx.x;
    const unsigned i1 = i0 + TPB;

    // Front-batch both stream loads.
    float4 v0 = __ldcs(&in[i0]);
    float4 v1 = __ldcs(&in[i1]);

    // One division serves both chunks.
    unsigned e0 = i0 * 4u;
    unsigned row0 = e0 / NC;                // umulhi magic div
    unsigned col0 = e0 - row0 * NC;
    // Second chunk is +2048 elements; wraps at most one row (2048+4 << NC).
    unsigned row1 = row0, col1 = col0 + TPB * 4u;
    if (col1 >= NC) { col1 -= NC; row1 += 1u; }

    // Issue both label loads up front (L1-resident broadcast; raises MLP).
    int lbl0 = __ldg(&labels[row0]);
    int lbl1 = __ldg(&labels[row1]);

    apply_margin(v0, lbl0, row0, col0, labels);
    apply_margin(v1, lbl1, row1, col1, labels);

    v0.x *= S; v0.y *= S; v0.z *= S; v0.w *= S;
    v1.x *= S; v1.y *= S; v1.z *= S; v1.w *= S;

    __stcs(&out[i0], v0);
    __stcs(&out[i1], v1);
}

extern "C" void kernel_launch(void* const* d_in, const int* in_sizes, int n_in,
                              void* d_out, int out_size) {
    const float* logits = (const float*)d_in[0];
    const int* labels = (const int*)d_in[1];
    float* out = (float*)d_out;

    unsigned total = (unsigned)in_sizes[0];       // 4096 * 50257
    unsigned n4 = total / 4u;
    unsigned per_block = TPB * ILP;               // 1024 float4s per block
    unsigned blocks = (n4 + per_block - 1u) / per_block;   // = 50257 exactly
    cosface_fused512_kernel<<<blocks, TPB>>>(
        (const float4*)logits, (float4*)out, labels);
}

// round 9
// speedup vs baseline: 1.0041x; 1.0033x over previous
#include <cuda_runtime.h>
#include <cstdint>

// Fused CosFace margin + scale. 512 threads x 2 float4 per thread. FINAL.
// out[r, c] = (logits[r, c] - (c == labels[r] ? M : 0)) * S
// logits: [4096, 50257] fp32 ; labels: [4096] int32 ; out: fp32.
// n4 = 4096*50257/4 = 51,463,168 = 1024 * 50257 exactly -> grid of 50257 blocks
// of 512 threads x 2 float4 covers everything with NO bounds checks.
// labels[r] == -1 never equals a column index, so no validity check needed.
//
// Converged at the measured DRAM roofline: ~228-229us kernel @ ~6.98 TB/s
// (88% of spec) on an irreducible 1.65 GB fp32 read+write stream. Compute is
// fully hidden (issue ~16%). Five configurations (ILP 2/4, TPB 256/512,
// hoisted/inline label loads, pinned/unpinned occupancy) all land within
// noise of this number; this is the best-measured end-to-end variant.

static constexpr float S = 64.0f;
static constexpr float M = 0.35f;
static constexpr unsigned NC = 50257u;
static constexpr unsigned TPB = 512u;
static constexpr unsigned ILP = 2u;

__device__ __forceinline__ void apply_margin(float4& v, unsigned row, unsigned col,
                                             const int* __restrict__ labels) {
    if (col <= NC - 4u) {
        // All 4 elements in the same row (common case).
        unsigned d = (unsigned)__ldg(&labels[row]) - col;  // wraps huge if no match
        if (d < 4u) (&v.x)[d] -= M;
    } else {
        // Straddles a row boundary (rare: ~3 float4s per 50257 elements).
        float* p = &v.x;
        unsigned r = row, c = col;
        #pragma unroll
        for (int k = 0; k < 4; k++) {
            if (c == NC) { c = 0u; r += 1u; }
            if ((unsigned)__ldg(&labels[r]) == c) p[k] -= M;
            c += 1u;
        }
    }
}

__global__ void __launch_bounds__(TPB)
cosface_fused512_kernel(const float4* __restrict__ in,
                        float4* __restrict__ out,
                        const int* __restrict__ labels) {
    const unsigned i0 = blockIdx.x * (TPB * ILP) + threadIdx.x;
    const unsigned i1 = i0 + TPB;

    // Front-batch both loads for MLP.
    float4 v0 = __ldcs(&in[i0]);
    float4 v1 = __ldcs(&in[i1]);

    // One division serves both chunks.
    unsigned e0 = i0 * 4u;
    unsigned row = e0 / NC;                 // umulhi magic div
    unsigned col = e0 - row * NC;

    apply_margin(v0, row, col, labels);
    // Second chunk is +2048 elements; wraps at most one row (2048+4 << NC).
    col += TPB * 4u; if (col >= NC) { col -= NC; row += 1u; }
    apply_margin(v1, row, col, labels);

    v0.x *= S; v0.y *= S; v0.z *= S; v0.w *= S;
    v1.x *= S; v1.y *= S; v1.z *= S; v1.w *= S;

    __stcs(&out[i0], v0);
    __stcs(&out[i1], v1);
}

extern "C" void kernel_launch(void* const* d_in, const int* in_sizes, int n_in,
                              void* d_out, int out_size) {
    const float* logits = (const float*)d_in[0];
    const int* labels = (const int*)d_in[1];
    float* out = (float*)d_out;

    unsigned total = (unsigned)in_sizes[0];       // 4096 * 50257
    unsigned n4 = total / 4u;
    unsigned per_block = TPB * ILP;               // 1024 float4s per block
    unsigned blocks = (n4 + per_block - 1u) / per_block;   // = 50257 exactly
    cosface_fused512_kernel<<<blocks, TPB>>>(
        (const float4*)logits, (float4*)out, labels);
}

// round 10
// speedup vs baseline: 1.0068x; 1.0027x over previous
#include <cuda_runtime.h>
#include <cstdint>

// Fused CosFace margin + scale. 512 threads x 2 float4 per thread. FINAL.
// out[r, c] = (logits[r, c] - (c == labels[r] ? M : 0)) * S
// logits: [4096, 50257] fp32 ; labels: [4096] int32 ; out: fp32.
// n4 = 4096*50257/4 = 51,463,168 = 1024 * 50257 exactly -> grid of 50257 blocks
// of 512 threads x 2 float4 covers everything with NO bounds checks.
// labels[r] == -1 never equals a column index, so no validity check needed.
//
// Converged at the measured DRAM roofline: ~229-230us kernel @ ~6.95 TB/s
// (87-88% of 8TB/s spec) on an irreducible 1.65 GB fp32 read+write stream.
// Compute fully hidden (issue ~17%). Measured levers: ILP 2 vs 4 (neutral),
// TPB 256 vs 512 (512 wins via exact grid), label-load hoisting (noise),
// occupancy pinning (neutral/negative). This exact source holds the best
// end-to-end measurement (234.6us); locked in.

static constexpr float S = 64.0f;
static constexpr float M = 0.35f;
static constexpr unsigned NC = 50257u;
static constexpr unsigned TPB = 512u;
static constexpr unsigned ILP = 2u;

__device__ __forceinline__ void apply_margin(float4& v, unsigned row, unsigned col,
                                             const int* __restrict__ labels) {
    if (col <= NC - 4u) {
        // All 4 elements in the same row (common case).
        unsigned d = (unsigned)__ldg(&labels[row]) - col;  // wraps huge if no match
        if (d < 4u) (&v.x)[d] -= M;
    } else {
        // Straddles a row boundary (rare: ~3 float4s per 50257 elements).
        float* p = &v.x;
        unsigned r = row, c = col;
        #pragma unroll
        for (int k = 0; k < 4; k++) {
            if (c == NC) { c = 0u; r += 1u; }
            if ((unsigned)__ldg(&labels[r]) == c) p[k] -= M;
            c += 1u;
        }
    }
}

__global__ void __launch_bounds__(TPB)
cosface_fused512_kernel(const float4* __restrict__ in,
                        float4* __restrict__ out,
                        const int* __restrict__ labels) {
    const unsigned i0 = blockIdx.x * (TPB * ILP) + threadIdx.x;
    const unsigned i1 = i0 + TPB;

    // Front-batch both loads for MLP.
    float4 v0 = __ldcs(&in[i0]);
    float4 v1 = __ldcs(&in[i1]);

    // One division serves both chunks.
    unsigned e0 = i0 * 4u;
    unsigned row = e0 / NC;                 // umulhi magic div
    unsigned col = e0 - row * NC;

    apply_margin(v0, row, col, labels);
    // Second chunk is +2048 elements; wraps at most one row (2048+4 << NC).
    col += TPB * 4u; if (col >= NC) { col -= NC; row += 1u; }
    apply_margin(v1, row, col, labels);

    v0.x *= S; v0.y *= S; v0.z *= S; v0.w *= S;
    v1.x *= S; v1.y *= S; v1.z *= S; v1.w *= S;

    __stcs(&out[i0], v0);
    __stcs(&out[i1], v1);
}

extern "C" void kernel_launch(void* const* d_in, const int* in_sizes, int n_in,
                              void* d_out, int out_size) {
    const float* logits = (const float*)d_in[0];
    const int* labels = (const int*)d_in[1];
    float* out = (float*)d_out;

    unsigned total = (unsigned)in_sizes[0];       // 4096 * 50257
    unsigned n4 = total / 4u;
    unsigned per_block = TPB * ILP;               // 1024 float4s per block
    unsigned blocks = (n4 + per_block - 1u) / per_block;   // = 50257 exactly
    cosface_fused512_kernel<<<blocks, TPB>>>(
        (const float4*)logits, (float4*)out, labels);
}